// round 5
// baseline (speedup 1.0000x reference)
#include <cuda_runtime.h>
#include <stdint.h>

// Problem constants (fixed dataset shapes)
#define HID    256
#define GEO    13
#define DIN    781          // 3*HID + GEO
#define NBR    4
#define DEPTHL 3
#define EPSB   1e-5f
#define E_CAP  100000

// Tiling
#define TM   64             // edges per tile
#define KC   32             // K chunk
#define NTH  256            // threads per block
#define HPAD 260            // padded h row stride (floats)
#define XPAD 36             // padded X chunk row stride (floats)

__device__ int g_cnt[NBR];
__device__ int g_list[NBR * E_CAP];

__global__ void zero_cnt_kernel() {
    if (threadIdx.x < NBR) g_cnt[threadIdx.x] = 0;
}

__global__ void bucket_kernel(const int* __restrict__ edx_ij,
                              const int* __restrict__ edx_jk,
                              const int* __restrict__ nei, int E) {
    int e = blockIdx.x * blockDim.x + threadIdx.x;
    if (e >= E) return;
    int Ein = *nei;
    int br = ((edx_ij[e] < Ein) ? 0 : 2) + ((edx_jk[e] < Ein) ? 0 : 1);
    int pos = atomicAdd(&g_cnt[br], 1);
    g_list[br * E_CAP + pos] = e;
}

// BN(eval)+ReLU epilogue: acc -> hA (shared). Folds bias into shift.
__device__ __forceinline__ void bn_relu_store(
    float acc[8][8], float* __restrict__ hA, int row0, int col0,
    const float* __restrict__ gm, const float* __restrict__ bt,
    const float* __restrict__ mn, const float* __restrict__ vr,
    const float* __restrict__ bias)
{
    float scv[8], shv[8];
    #pragma unroll
    for (int n = 0; n < 8; n++) {
        int c = col0 + n;
        float sc = gm[c] * rsqrtf(vr[c] + EPSB);
        scv[n] = sc;
        shv[n] = bt[c] - mn[c] * sc + bias[c] * sc;
    }
    #pragma unroll
    for (int m = 0; m < 8; m++) {
        float t[8];
        #pragma unroll
        for (int n = 0; n < 8; n++) {
            float h = fmaf(acc[m][n], scv[n], shv[n]);
            t[n] = fmaxf(h, 0.f);
            acc[m][n] = 0.f;
        }
        *(float4*)(hA + (row0 + m) * HPAD + col0)     = make_float4(t[0], t[1], t[2], t[3]);
        *(float4*)(hA + (row0 + m) * HPAD + col0 + 4) = make_float4(t[4], t[5], t[6], t[7]);
    }
}

__global__ void __launch_bounds__(NTH, 2)
spnn_kernel(const float* __restrict__ nf,
            const float* __restrict__ geo,
            const int*   __restrict__ ei,     // [3, E]
            const float* __restrict__ att,
            const float* __restrict__ W0,     // [4, DIN, HID]
            const float* __restrict__ b0,     // [4, HID]
            const float* __restrict__ Wh,     // [4, DEPTH, HID, HID]
            const float* __restrict__ bh,     // [4, DEPTH, HID]
            const float* __restrict__ gamma,  // [4, DEPTH+1, HID]
            const float* __restrict__ beta,
            const float* __restrict__ rmean,
            const float* __restrict__ rvar,
            float* __restrict__ out,          // [N, HID]
            int E)
{
    const int br  = blockIdx.y;
    const int cnt = g_cnt[br];
    const int m0  = blockIdx.x * TM;
    if (m0 >= cnt) return;

    extern __shared__ float smem[];
    float* hA = smem;                       // TM * HPAD
    float* Ws = hA + TM * HPAD;             // KC * HID
    float* Xs = Ws + KC * HID;              // TM * XPAD
    int*   sI = (int*)(Xs + TM * XPAD);
    int*   sJ = sI + TM;
    int*   sK = sJ + TM;
    int*   sE = sK + TM;

    const int tid = threadIdx.x;
    if (tid < TM) {
        int idx = m0 + tid;
        int e = (idx < cnt) ? g_list[br * E_CAP + idx] : -1;
        sE[tid] = e;
        int ee = (e >= 0) ? e : 0;
        sI[tid] = ei[ee];
        sJ[tid] = ei[E + ee];
        sK[tid] = ei[2 * E + ee];
    }
    __syncthreads();

    const int tr = tid >> 5, tc = tid & 31;
    const int row0 = tr << 3, col0 = tc << 3;

    float acc[8][8];
    #pragma unroll
    for (int m = 0; m < 8; m++)
        #pragma unroll
        for (int n = 0; n < 8; n++) acc[m][n] = 0.f;

    // ---------------- Layer 0: x[E, DIN] @ W0[br] ----------------
    const float* W0b  = W0 + (size_t)br * DIN * HID;
    const int wcol4 = tid & 63;   // which float4 column group (0..63)
    const int wrow  = tid >> 6;   // base row in chunk (0..3)

    for (int kc0 = 0; kc0 < DIN; kc0 += KC) {
        // Stage weights chunk Ws[kk][c]
        #pragma unroll
        for (int it = 0; it < 8; it++) {
            int kk = wrow + (it << 2);
            int gk = kc0 + kk;
            float4 w = make_float4(0.f, 0.f, 0.f, 0.f);
            if (gk < DIN) w = *(const float4*)(W0b + (size_t)gk * HID + (wcol4 << 2));
            *(float4*)(Ws + kk * HID + (wcol4 << 2)) = w;
        }
        // Stage gathered activations Xs[r][kk]
        if (kc0 < 3 * HID) {
            int seg = kc0 >> 8;                // 0:i  1:j  2:k
            int off = kc0 & 255;
            int c4  = tid & 7;
            int rb  = tid >> 3;
            const int* sidx = (seg == 0) ? sI : (seg == 1) ? sJ : sK;
            #pragma unroll
            for (int it = 0; it < 2; it++) {
                int r = rb + (it << 5);
                int nidx = sidx[r];
                float4 v = *(const float4*)(nf + (size_t)nidx * HID + off + (c4 << 2));
                *(float4*)(Xs + r * XPAD + (c4 << 2)) = v;
            }
        } else {
            // geo chunk (13 valid cols, zero-pad to 32)
            int c  = tid & 31;
            int rb = tid >> 5;
            #pragma unroll
            for (int it = 0; it < 8; it++) {
                int r = rb + (it << 3);
                float v = 0.f;
                if (c < GEO) {
                    int e = sE[r]; if (e < 0) e = 0;
                    v = geo[(size_t)e * GEO + c];
                }
                Xs[r * XPAD + c] = v;
            }
        }
        __syncthreads();

        #pragma unroll 4
        for (int kk = 0; kk < KC; kk++) {
            float a[8], b[8];
            #pragma unroll
            for (int m = 0; m < 8; m++) a[m] = Xs[(row0 + m) * XPAD + kk];
            float4 bv0 = *(float4*)(Ws + kk * HID + col0);
            float4 bv1 = *(float4*)(Ws + kk * HID + col0 + 4);
            b[0] = bv0.x; b[1] = bv0.y; b[2] = bv0.z; b[3] = bv0.w;
            b[4] = bv1.x; b[5] = bv1.y; b[6] = bv1.z; b[7] = bv1.w;
            #pragma unroll
            for (int m = 0; m < 8; m++)
                #pragma unroll
                for (int n = 0; n < 8; n++)
                    acc[m][n] = fmaf(a[m], b[n], acc[m][n]);
        }
        __syncthreads();
    }

    // Layer 0 epilogue
    {
        const int ly = 0;
        size_t o = ((size_t)br * (DEPTHL + 1) + ly) << 8;
        bn_relu_store(acc, hA, row0, col0,
                      gamma + o, beta + o, rmean + o, rvar + o,
                      b0 + ((size_t)br << 8));
    }
    __syncthreads();

    // ---------------- Hidden layers ----------------
    #pragma unroll 1
    for (int l = 0; l < DEPTHL; l++) {
        const float* Wl = Wh + ((size_t)(br * DEPTHL + l)) * HID * HID;
        #pragma unroll 1
        for (int kc0 = 0; kc0 < HID; kc0 += KC) {
            #pragma unroll
            for (int it = 0; it < 8; it++) {
                int kk = wrow + (it << 2);
                *(float4*)(Ws + kk * HID + (wcol4 << 2)) =
                    *(const float4*)(Wl + (size_t)(kc0 + kk) * HID + (wcol4 << 2));
            }
            __syncthreads();
            #pragma unroll 4
            for (int kk = 0; kk < KC; kk++) {
                float a[8], b[8];
                #pragma unroll
                for (int m = 0; m < 8; m++) a[m] = hA[(row0 + m) * HPAD + kc0 + kk];
                float4 bv0 = *(float4*)(Ws + kk * HID + col0);
                float4 bv1 = *(float4*)(Ws + kk * HID + col0 + 4);
                b[0] = bv0.x; b[1] = bv0.y; b[2] = bv0.z; b[3] = bv0.w;
                b[4] = bv1.x; b[5] = bv1.y; b[6] = bv1.z; b[7] = bv1.w;
                #pragma unroll
                for (int m = 0; m < 8; m++)
                    #pragma unroll
                    for (int n = 0; n < 8; n++)
                        acc[m][n] = fmaf(a[m], b[n], acc[m][n]);
            }
            __syncthreads();
        }

        int ly = l + 1;
        size_t o = ((size_t)br * (DEPTHL + 1) + ly) << 8;
        if (l < DEPTHL - 1) {
            bn_relu_store(acc, hA, row0, col0,
                          gamma + o, beta + o, rmean + o, rvar + o,
                          bh + (size_t)(br * DEPTHL + l) * HID);
            __syncthreads();
        } else {
            // Final: BN + ReLU, leaky_relu is identity on >=0, scale by att, scatter-add.
            const float* gm = gamma + o;
            const float* bt = beta + o;
            const float* mn = rmean + o;
            const float* vr = rvar + o;
            const float* bs = bh + (size_t)(br * DEPTHL + l) * HID;
            float scv[8], shv[8];
            #pragma unroll
            for (int n = 0; n < 8; n++) {
                int c = col0 + n;
                float sc = gm[c] * rsqrtf(vr[c] + EPSB);
                scv[n] = sc;
                shv[n] = bt[c] - mn[c] * sc + bs[c] * sc;
            }
            float ab = __ldg(att + br);
            #pragma unroll
            for (int m = 0; m < 8; m++) {
                int rr = row0 + m;
                int e = sE[rr];
                if (e < 0) continue;
                size_t obase = (size_t)sI[rr] * HID + col0;
                #pragma unroll
                for (int n = 0; n < 8; n++) {
                    float h = fmaf(acc[m][n], scv[n], shv[n]);
                    h = fmaxf(h, 0.f);           // ReLU; leaky_relu(h>=0) == h
                    atomicAdd(out + obase + n, h * ab);
                }
            }
        }
    }
}

extern "C" void kernel_launch(void* const* d_in, const int* in_sizes, int n_in,
                              void* d_out, int out_size) {
    const float* nf  = (const float*)d_in[0];
    const float* geo = (const float*)d_in[1];
    const int*   ei  = (const int*)d_in[2];
    const int*   eij = (const int*)d_in[3];
    const int*   ejk = (const int*)d_in[4];
    const float* att = (const float*)d_in[5];
    const float* W0  = (const float*)d_in[6];
    const float* b0  = (const float*)d_in[7];
    const float* Wh  = (const float*)d_in[8];
    const float* bh  = (const float*)d_in[9];
    const float* gam = (const float*)d_in[10];
    const float* bet = (const float*)d_in[11];
    const float* rme = (const float*)d_in[12];
    const float* rva = (const float*)d_in[13];
    const int*   nei = (const int*)d_in[14];

    int E = in_sizes[3];
    if (E > E_CAP) E = E_CAP;
    float* out = (float*)d_out;

    cudaMemsetAsync(out, 0, (size_t)out_size * sizeof(float));

    zero_cnt_kernel<<<1, 32>>>();
    bucket_kernel<<<(E + 255) / 256, 256>>>(eij, ejk, nei, E);

    const int smem_bytes = (TM * HPAD + KC * HID + TM * XPAD) * 4 + 4 * TM * 4;
    cudaFuncSetAttribute(spnn_kernel, cudaFuncAttributeMaxDynamicSharedMemorySize, smem_bytes);

    dim3 grid((E + TM - 1) / TM, NBR);
    spnn_kernel<<<grid, NTH, smem_bytes>>>(nf, geo, ei, att, W0, b0, Wh, bh,
                                           gam, bet, rme, rva, out, E);
}

// round 9
// speedup vs baseline: 1.6303x; 1.6303x over previous
#include <cuda_runtime.h>
#include <cuda_bf16.h>
#include <stdint.h>

// ---------------- problem constants ----------------
#define HID    256
#define GEO    13
#define DIN    781
#define NBR    4
#define DEPTHL 3
#define EPSB   1e-5f
#define E_CAP  100000

// ---------------- tiling ----------------
#define TM    64
#define NTH   256
#define KCH   64
#define L0C   13                      // layer-0 K chunks (13*64 = 832 >= 781)
#define KPAD0 (L0C*KCH)               // 832
#define KPB   (KPAD0 + DEPTHL*HID)    // 1600 packed K cols per branch

// ---------------- smem layout (bytes) ----------------
#define OFF_SI  0
#define OFF_SJ  256
#define OFF_SK  512
#define OFF_SE  768
#define OFF_SS  1024                  // BN scale [256] f32
#define OFF_SH  2048                  // BN shift [256] f32
#define OFF_XH  4096                  // layer0 A chunk hi: 64 x 128B = 8KB
#define OFF_XL  (OFF_XH + 8192)
#define OFF_HH  (OFF_XL + 8192)       // h hi: 64 x 512B = 32KB
#define OFF_HL  (OFF_HH + 32768)
#define OFF_BH  (OFF_HL + 32768)      // B hi double buffer: 2 x 32KB
#define OFF_BL  (OFF_BH + 65536)      // B lo double buffer: 2 x 32KB
#define SMEM_BYTES (OFF_BL + 65536)   // 217088

__device__ int g_cnt[NBR];
__device__ int g_list[NBR * E_CAP];
__device__ __align__(16) __nv_bfloat16 g_Whi[NBR * KPB * HID];
__device__ __align__(16) __nv_bfloat16 g_Wlo[NBR * KPB * HID];

// ---------------- helpers ----------------
__device__ __forceinline__ uint32_t smem_u32(const void* p) {
    uint32_t a;
    asm("{ .reg .u64 t; cvta.to.shared.u64 t, %1; cvt.u32.u64 %0, t; }" : "=r"(a) : "l"(p));
    return a;
}

__device__ __forceinline__ void cp16(uint32_t dst, const void* src) {
    asm volatile("cp.async.cg.shared.global [%0], [%1], 16;" :: "r"(dst), "l"(src) : "memory");
}
#define CP_COMMIT() asm volatile("cp.async.commit_group;" ::: "memory")
template<int N> __device__ __forceinline__ void cp_wait() {
    asm volatile("cp.async.wait_group %0;" :: "n"(N) : "memory");
}

__device__ __forceinline__ void ldsm4(uint32_t& r0, uint32_t& r1, uint32_t& r2, uint32_t& r3,
                                      uint32_t a) {
    asm volatile("ldmatrix.sync.aligned.m8n8.x4.shared.b16 {%0,%1,%2,%3}, [%4];"
        : "=r"(r0), "=r"(r1), "=r"(r2), "=r"(r3) : "r"(a));
}

__device__ __forceinline__ void mma16816(float* c, const uint32_t* a, const uint32_t* b) {
    asm volatile("mma.sync.aligned.m16n8k16.row.col.f32.bf16.bf16.f32 "
        "{%0,%1,%2,%3}, {%4,%5,%6,%7}, {%8,%9}, {%0,%1,%2,%3};"
        : "+f"(c[0]), "+f"(c[1]), "+f"(c[2]), "+f"(c[3])
        : "r"(a[0]), "r"(a[1]), "r"(a[2]), "r"(a[3]), "r"(b[0]), "r"(b[1]));
}

__device__ __forceinline__ void cvt2(float a, float b, uint32_t& h, uint32_t& l) {
    __nv_bfloat16 ha = __float2bfloat16(a), hb = __float2bfloat16(b);
    __nv_bfloat16 la = __float2bfloat16(a - __bfloat162float(ha));
    __nv_bfloat16 lb = __float2bfloat16(b - __bfloat162float(hb));
    h = (uint32_t)__bfloat16_as_ushort(ha) | ((uint32_t)__bfloat16_as_ushort(hb) << 16);
    l = (uint32_t)__bfloat16_as_ushort(la) | ((uint32_t)__bfloat16_as_ushort(lb) << 16);
}

// chunk-granular XOR swizzle (16B chunks, stride-agnostic: low 3 chunk bits XOR row&7)
__device__ __forceinline__ uint32_t swzoff(int row, int stride, int ch) {
    return (uint32_t)(row * stride) +
           ((uint32_t)((ch & ~7) | ((ch & 7) ^ (row & 7))) << 4);
}

// ---------------- small kernels ----------------
__global__ void zero_cnt_kernel() {
    if (threadIdx.x < NBR) g_cnt[threadIdx.x] = 0;
}

__global__ void bucket_kernel(const int* __restrict__ edx_ij,
                              const int* __restrict__ edx_jk,
                              const int* __restrict__ nei, int E) {
    int e = blockIdx.x * blockDim.x + threadIdx.x;
    if (e >= E) return;
    int Ein = *nei;
    int br = ((edx_ij[e] < Ein) ? 0 : 2) + ((edx_jk[e] < Ein) ? 0 : 1);
    int pos = atomicAdd(&g_cnt[br], 1);
    g_list[br * E_CAP + pos] = e;
}

// Transpose + bf16 hi/lo split of all weights into g_Whi/g_Wlo ([n][k] per branch).
__global__ void prep_w(const float* __restrict__ W0, const float* __restrict__ Wh) {
    int t = blockIdx.x * blockDim.x + threadIdx.x;
    const int per = KPB * HID;
    if (t >= NBR * per) return;
    int br = t / per, u = t % per;
    float w;
    if (u < KPAD0 * HID) {
        int n = u / KPAD0, k = u % KPAD0;
        w = (k < DIN) ? W0[(size_t)br * DIN * HID + (size_t)k * HID + n] : 0.f;
    } else {
        int v = u - KPAD0 * HID;
        int l = v / (HID * HID), v2 = v % (HID * HID);
        int n = v2 / HID, k = v2 % HID;
        w = Wh[(size_t)(br * DEPTHL + l) * HID * HID + (size_t)k * HID + n];
    }
    __nv_bfloat16 h = __float2bfloat16(w);
    __nv_bfloat16 lo = __float2bfloat16(w - __bfloat162float(h));
    g_Whi[t] = h;
    g_Wlo[t] = lo;
}

// ---------------- per-layer weight region ----------------
__device__ __forceinline__ void layer_w(int layer, int br, size_t& wbase, int& Kpad, int& nch) {
    if (layer == 0) { wbase = (size_t)br * KPB * HID; Kpad = KPAD0; nch = L0C; }
    else {
        wbase = (size_t)br * KPB * HID + (size_t)KPAD0 * HID + (size_t)(layer - 1) * HID * HID;
        Kpad = HID; nch = HID / KCH;
    }
}

__device__ __forceinline__ void prefetch_B(char* sm, int buf, size_t wbase, int Kpad,
                                           int kc, int tid) {
    int n = tid;  // 256 threads = 256 B rows
    const __nv_bfloat16* sh = g_Whi + wbase + (size_t)n * Kpad + kc * KCH;
    const __nv_bfloat16* sl = g_Wlo + wbase + (size_t)n * Kpad + kc * KCH;
    uint32_t dh = smem_u32(sm + OFF_BH + buf * 32768 + n * 128);
    uint32_t dl = smem_u32(sm + OFF_BL + buf * 32768 + n * 128);
    uint32_t x = (uint32_t)(n & 7) << 4;
    #pragma unroll
    for (int c = 0; c < 8; c++) {
        uint32_t off = ((uint32_t)c << 4) ^ x;
        cp16(dh + off, sh + c * 8);
        cp16(dl + off, sl + c * 8);
    }
}

// ---------------- main kernel ----------------
__global__ void __launch_bounds__(NTH, 1)
spnn_mma_kernel(const float* __restrict__ nf,
                const float* __restrict__ geo,
                const int*   __restrict__ ei,
                const float* __restrict__ att,
                const float* __restrict__ b0,
                const float* __restrict__ bh,
                const float* __restrict__ gamma,
                const float* __restrict__ beta,
                const float* __restrict__ rmean,
                const float* __restrict__ rvar,
                float* __restrict__ out,
                int E)
{
    const int br  = blockIdx.y;
    const int cnt = g_cnt[br];
    const int m0  = blockIdx.x * TM;
    if (m0 >= cnt) return;

    extern __shared__ char sm[];
    const int tid = threadIdx.x;
    const int wid = tid >> 5, lid = tid & 31;
    const int wm = wid & 1, wn = wid >> 1;   // 2 m-warps x 4 n-warps

    int*   sI = (int*)(sm + OFF_SI);
    int*   sJ = (int*)(sm + OFF_SJ);
    int*   sK = (int*)(sm + OFF_SK);
    int*   sE = (int*)(sm + OFF_SE);
    float* sS = (float*)(sm + OFF_SS);
    float* sHt = (float*)(sm + OFF_SH);

    if (tid < TM) {
        int idx = m0 + tid;
        int e = (idx < cnt) ? g_list[br * E_CAP + idx] : g_list[br * E_CAP];
        sE[tid] = e;
        sI[tid] = ei[e];
        sJ[tid] = ei[E + e];
        sK[tid] = ei[2 * E + e];
    }

    // prefetch first B chunk
    {
        size_t wb; int kp, nc;
        layer_w(0, br, wb, kp, nc);
        prefetch_B(sm, 0, wb, kp, 0, tid);
        CP_COMMIT();
    }

    // lane decomposition for ldmatrix addressing
    const int arow_loc = (lid & 7) + ((lid >> 3) & 1) * 8;
    const int achalf   = (lid >> 4) & 1;
    const int brow_loc = (lid & 7) + ((lid >> 4) & 1) * 8;
    const int bchalf   = (lid >> 3) & 1;
    const uint32_t smb = smem_u32(sm);

    float acc[2][8][4];
    #pragma unroll
    for (int mt = 0; mt < 2; mt++)
        #pragma unroll
        for (int nt = 0; nt < 8; nt++)
            #pragma unroll
            for (int q = 0; q < 4; q++) acc[mt][nt][q] = 0.f;

    int buf = 0;

    #pragma unroll 1
    for (int layer = 0; layer <= DEPTHL; layer++) {
        size_t wb; int kp, nch;
        layer_w(layer, br, wb, kp, nch);

        #pragma unroll 1
        for (int kc = 0; kc < nch; kc++) {
            // prefetch next chunk (possibly next layer's chunk 0)
            int nlayer = layer, nkc = kc + 1;
            bool have_next = true;
            if (nkc == nch) {
                if (layer == DEPTHL) have_next = false;
                else { nlayer = layer + 1; nkc = 0; }
            }
            if (have_next) {
                size_t wb2; int kp2, nc2;
                layer_w(nlayer, br, wb2, kp2, nc2);
                prefetch_B(sm, buf ^ 1, wb2, kp2, nkc, tid);
                CP_COMMIT();
                cp_wait<1>();
            } else {
                cp_wait<0>();
            }
            __syncthreads();

            // layer-0: gather + hi/lo split A chunk into xbuf
            if (layer == 0) {
                int r = tid >> 2, q = tid & 3;
                float x[16];
                if (kc < 12) {
                    int seg = kc >> 2;
                    int idx = (seg == 0) ? sI[r] : (seg == 1) ? sJ[r] : sK[r];
                    const float* src = nf + (size_t)idx * HID + (kc & 3) * KCH + q * 16;
                    #pragma unroll
                    for (int u = 0; u < 4; u++) {
                        float4 v = *(const float4*)(src + u * 4);
                        x[u*4+0] = v.x; x[u*4+1] = v.y; x[u*4+2] = v.z; x[u*4+3] = v.w;
                    }
                } else {
                    int e = sE[r];
                    #pragma unroll
                    for (int u = 0; u < 16; u++) {
                        int kg = q * 16 + u;
                        x[u] = (kg < GEO) ? geo[(size_t)e * GEO + kg] : 0.f;
                    }
                }
                uint32_t hw[8], lw[8];
                #pragma unroll
                for (int p = 0; p < 8; p++) cvt2(x[2*p], x[2*p+1], hw[p], lw[p]);
                #pragma unroll
                for (int hc = 0; hc < 2; hc++) {
                    uint32_t off = (uint32_t)(r * 128) +
                                   ((uint32_t)((q * 2 + hc) ^ (r & 7)) << 4);
                    *(uint4*)(sm + OFF_XH + off) = make_uint4(hw[hc*4+0], hw[hc*4+1], hw[hc*4+2], hw[hc*4+3]);
                    *(uint4*)(sm + OFF_XL + off) = make_uint4(lw[hc*4+0], lw[hc*4+1], lw[hc*4+2], lw[hc*4+3]);
                }
                __syncthreads();
            }

            // A source for this layer
            uint32_t aH, aL; int astr, acb;
            if (layer == 0) { aH = smb + OFF_XH; aL = smb + OFF_XL; astr = 128; acb = 0; }
            else           { aH = smb + OFF_HH; aL = smb + OFF_HL; astr = 512; acb = kc * 8; }
            uint32_t bHb = smb + OFF_BH + buf * 32768;
            uint32_t bLb = smb + OFF_BL + buf * 32768;

            #pragma unroll
            for (int kk = 0; kk < 4; kk++) {
                uint32_t ahi[2][4], alo[2][4];
                #pragma unroll
                for (int mt = 0; mt < 2; mt++) {
                    int row = wm * 32 + mt * 16 + arow_loc;
                    int ch  = acb + kk * 2 + achalf;
                    uint32_t off = swzoff(row, astr, ch);
                    ldsm4(ahi[mt][0], ahi[mt][1], ahi[mt][2], ahi[mt][3], aH + off);
                    ldsm4(alo[mt][0], alo[mt][1], alo[mt][2], alo[mt][3], aL + off);
                }
                uint32_t bhi[8][2], blo[8][2];
                #pragma unroll
                for (int ntp = 0; ntp < 4; ntp++) {
                    int row = wn * 64 + ntp * 16 + brow_loc;
                    int ch  = kk * 2 + bchalf;
                    uint32_t off = (uint32_t)(row * 128) + ((uint32_t)(ch ^ (row & 7)) << 4);
                    ldsm4(bhi[2*ntp][0], bhi[2*ntp][1], bhi[2*ntp+1][0], bhi[2*ntp+1][1], bHb + off);
                    ldsm4(blo[2*ntp][0], blo[2*ntp][1], blo[2*ntp+1][0], blo[2*ntp+1][1], bLb + off);
                }
                #pragma unroll
                for (int mt = 0; mt < 2; mt++)
                    #pragma unroll
                    for (int nt = 0; nt < 8; nt++) {
                        mma16816(acc[mt][nt], ahi[mt], bhi[nt]);
                        mma16816(acc[mt][nt], alo[mt], bhi[nt]);
                        mma16816(acc[mt][nt], ahi[mt], blo[nt]);
                    }
            }
            __syncthreads();
            buf ^= 1;
        }

        // BN params for this layer
        {
            int c = tid;
            size_t o = ((size_t)br * (DEPTHL + 1) + layer) * HID + c;
            float sc = gamma[o] * rsqrtf(rvar[o] + EPSB);
            float bias = (layer == 0) ? b0[br * HID + c]
                                      : bh[(size_t)(br * DEPTHL + layer - 1) * HID + c];
            sS[c] = sc;
            sHt[c] = beta[o] - rmean[o] * sc + bias * sc;
        }
        __syncthreads();

        const bool final = (layer == DEPTHL);
        float attb = final ? att[br] : 0.f;
        #pragma unroll
        for (int mt = 0; mt < 2; mt++) {
            int r0 = wm * 32 + mt * 16 + (lid >> 2);
            int r1 = r0 + 8;
            #pragma unroll
            for (int nt = 0; nt < 8; nt++) {
                float* c = acc[mt][nt];
                int j0 = wn * 64 + nt * 8 + (lid & 3) * 2;
                float sc0 = sS[j0], sc1 = sS[j0 + 1];
                float h0 = sHt[j0], h1 = sHt[j0 + 1];
                float f00 = fmaxf(fmaf(c[0], sc0, h0), 0.f);
                float f01 = fmaxf(fmaf(c[1], sc1, h1), 0.f);
                float f10 = fmaxf(fmaf(c[2], sc0, h0), 0.f);
                float f11 = fmaxf(fmaf(c[3], sc1, h1), 0.f);
                c[0] = c[1] = c[2] = c[3] = 0.f;
                if (!final) {
                    uint32_t hv0, lv0, hv1, lv1;
                    cvt2(f00, f01, hv0, lv0);
                    cvt2(f10, f11, hv1, lv1);
                    int ch = j0 >> 3;
                    uint32_t o0 = swzoff(r0, 512, ch) + (uint32_t)((j0 & 7) * 2);
                    uint32_t o1 = swzoff(r1, 512, ch) + (uint32_t)((j0 & 7) * 2);
                    *(uint32_t*)(sm + OFF_HH + o0) = hv0;
                    *(uint32_t*)(sm + OFF_HL + o0) = lv0;
                    *(uint32_t*)(sm + OFF_HH + o1) = hv1;
                    *(uint32_t*)(sm + OFF_HL + o1) = lv1;
                } else {
                    if (m0 + r0 < cnt) {
                        float* op = out + (size_t)sI[r0] * HID + j0;
                        atomicAdd(op,     f00 * attb);
                        atomicAdd(op + 1, f01 * attb);
                    }
                    if (m0 + r1 < cnt) {
                        float* op = out + (size_t)sI[r1] * HID + j0;
                        atomicAdd(op,     f10 * attb);
                        atomicAdd(op + 1, f11 * attb);
                    }
                }
            }
        }
        __syncthreads();
    }
}

extern "C" void kernel_launch(void* const* d_in, const int* in_sizes, int n_in,
                              void* d_out, int out_size) {
    const float* nf  = (const float*)d_in[0];
    const float* geo = (const float*)d_in[1];
    const int*   ei  = (const int*)d_in[2];
    const int*   eij = (const int*)d_in[3];
    const int*   ejk = (const int*)d_in[4];
    const float* att = (const float*)d_in[5];
    const float* W0  = (const float*)d_in[6];
    const float* b0  = (const float*)d_in[7];
    const float* Wh  = (const float*)d_in[8];
    const float* bh  = (const float*)d_in[9];
    const float* gam = (const float*)d_in[10];
    const float* bet = (const float*)d_in[11];
    const float* rme = (const float*)d_in[12];
    const float* rva = (const float*)d_in[13];
    const int*   nei = (const int*)d_in[14];

    int E = in_sizes[3];
    if (E > E_CAP) E = E_CAP;
    float* out = (float*)d_out;

    cudaMemsetAsync(out, 0, (size_t)out_size * sizeof(float));

    zero_cnt_kernel<<<1, 32>>>();
    bucket_kernel<<<(E + 255) / 256, 256>>>(eij, ejk, nei, E);

    int prep_total = NBR * KPB * HID;
    prep_w<<<(prep_total + 255) / 256, 256>>>(W0, Wh);

    cudaFuncSetAttribute(spnn_mma_kernel,
                         cudaFuncAttributeMaxDynamicSharedMemorySize, SMEM_BYTES);
    dim3 grid((E + TM - 1) / TM, NBR);
    spnn_mma_kernel<<<grid, NTH, SMEM_BYTES>>>(nf, geo, ei, att, b0, bh,
                                               gam, bet, rme, rva, out, E);
}

// round 10
// speedup vs baseline: 2.9764x; 1.8257x over previous
#include <cuda_runtime.h>
#include <cuda_bf16.h>
#include <stdint.h>

// ---------------- problem constants ----------------
#define HID    256
#define GEO    13
#define DIN    781
#define NBR    4
#define DEPTHL 3
#define EPSB   1e-5f
#define E_CAP  100000

// ---------------- tiling ----------------
#define TM    64
#define NTH   256
#define NG0   49                      // layer-0 k16 groups (49*16=784 >= 781)
#define KPAD0 (NG0*16)
#define NGH   16                      // k16 groups per hidden layer
#define NGT   (NG0 + DEPTHL*NGH)      // 97 groups per branch
#define KPB   (NGT*16)                // 1552
#define GRP_ELEMS 4096                // 16 ntiles x 32 rows x 8 bf16

// ---------------- smem offsets (bytes) ----------------
#define OFF_SI 0
#define OFF_SJ 256
#define OFF_SK 512
#define OFF_SE 768
#define OFF_SS 1024                   // BN scale [256] f32
#define OFF_SH 2048                   // BN shift [256] f32
#define OFF_X  3072                   // 2 planes x 2048B (layer-0 A chunk, native)
#define OFF_H  (OFF_X + 4096)         // 2 planes x 32768B (activations, native)
#define OFF_B  (OFF_H + 65536)        // 2 bufs x (2 planes x 8192B)
#define SMEM_BYTES (OFF_B + 32768)    // 105472

__device__ int g_cnt[NBR];
__device__ int g_list[NBR * E_CAP];
// packed ldmatrix-native weights: [br][group][ntile][32 rows][8 bf16]
__device__ __align__(16) __nv_bfloat16 g_Whi[NBR * NGT * GRP_ELEMS];
__device__ __align__(16) __nv_bfloat16 g_Wlo[NBR * NGT * GRP_ELEMS];

// ---------------- helpers ----------------
__device__ __forceinline__ uint32_t smem_u32(const void* p) {
    uint32_t a;
    asm("{ .reg .u64 t; cvta.to.shared.u64 t, %1; cvt.u32.u64 %0, t; }" : "=r"(a) : "l"(p));
    return a;
}
__device__ __forceinline__ void cp16(uint32_t dst, const void* src) {
    asm volatile("cp.async.cg.shared.global [%0], [%1], 16;" :: "r"(dst), "l"(src) : "memory");
}
#define CP_COMMIT() asm volatile("cp.async.commit_group;" ::: "memory")
template<int N> __device__ __forceinline__ void cp_wait() {
    asm volatile("cp.async.wait_group %0;" :: "n"(N) : "memory");
}
__device__ __forceinline__ void ldsm4(uint32_t* r, uint32_t a) {
    asm volatile("ldmatrix.sync.aligned.m8n8.x4.shared.b16 {%0,%1,%2,%3}, [%4];"
        : "=r"(r[0]), "=r"(r[1]), "=r"(r[2]), "=r"(r[3]) : "r"(a));
}
__device__ __forceinline__ void mma16816(float* c, const uint32_t* a, const uint32_t* b) {
    asm volatile("mma.sync.aligned.m16n8k16.row.col.f32.bf16.bf16.f32 "
        "{%0,%1,%2,%3}, {%4,%5,%6,%7}, {%8,%9}, {%0,%1,%2,%3};"
        : "+f"(c[0]), "+f"(c[1]), "+f"(c[2]), "+f"(c[3])
        : "r"(a[0]), "r"(a[1]), "r"(a[2]), "r"(a[3]), "r"(b[0]), "r"(b[1]));
}
__device__ __forceinline__ void cvt2(float a, float b, uint32_t& h, uint32_t& l) {
    __nv_bfloat16 ha = __float2bfloat16(a), hb = __float2bfloat16(b);
    __nv_bfloat16 la = __float2bfloat16(a - __bfloat162float(ha));
    __nv_bfloat16 lb = __float2bfloat16(b - __bfloat162float(hb));
    h = (uint32_t)__bfloat16_as_ushort(ha) | ((uint32_t)__bfloat16_as_ushort(hb) << 16);
    l = (uint32_t)__bfloat16_as_ushort(la) | ((uint32_t)__bfloat16_as_ushort(lb) << 16);
}

// ---------------- small kernels ----------------
__global__ void zero_cnt_kernel() {
    if (threadIdx.x < NBR) g_cnt[threadIdx.x] = 0;
}
__global__ void bucket_kernel(const int* __restrict__ edx_ij,
                              const int* __restrict__ edx_jk,
                              const int* __restrict__ nei, int E) {
    int e = blockIdx.x * blockDim.x + threadIdx.x;
    if (e >= E) return;
    int Ein = *nei;
    int br = ((edx_ij[e] < Ein) ? 0 : 2) + ((edx_jk[e] < Ein) ? 0 : 1);
    int pos = atomicAdd(&g_cnt[br], 1);
    g_list[br * E_CAP + pos] = e;
}

// Pack weights transposed + hi/lo split into ldmatrix-native layout.
__global__ void prep_w(const float* __restrict__ W0, const float* __restrict__ Wh) {
    int t = blockIdx.x * blockDim.x + threadIdx.x;
    if (t >= NBR * KPB * HID) return;
    int n = t & 255;
    int rem = t >> 8;
    int k = rem % KPB;
    int br = rem / KPB;
    float w;
    if (k < KPAD0) {
        w = (k < DIN) ? W0[((size_t)br * DIN + k) * HID + n] : 0.f;
    } else {
        int kk = k - KPAD0;
        int l = kk >> 8, k2 = kk & 255;
        w = Wh[(((size_t)(br * DEPTHL + l)) * HID + k2) * HID + n];
    }
    int g  = k >> 4;
    int kl = k & 15;
    int kh = kl >> 3, kb = kl & 7;
    int lrow = (n & 7) + ((n >> 3) & 1) * 16 + kh * 8;
    int ntile = n >> 4;
    size_t off = (((size_t)(br * NGT + g)) * 16 + ntile) * 256 + lrow * 8 + kb;
    __nv_bfloat16 h = __float2bfloat16(w);
    g_Whi[off] = h;
    g_Wlo[off] = __float2bfloat16(w - __bfloat162float(h));
}

__device__ __forceinline__ void prefetch_B(char* sm, int buf, int br, int g, int tid) {
    size_t base = (size_t)(br * NGT + g) * GRP_ELEMS;   // bf16 elems
    uint32_t d = smem_u32(sm + OFF_B + buf * 16384) + (uint32_t)tid * 16;
    const char* sh = (const char*)(g_Whi + base) + tid * 16;
    const char* sl = (const char*)(g_Wlo + base) + tid * 16;
    cp16(d,         sh);
    cp16(d + 4096,  sh + 4096);
    cp16(d + 8192,  sl);
    cp16(d + 12288, sl + 4096);
}

__device__ __forceinline__ int layer_gbase(int layer) {
    return (layer == 0) ? 0 : NG0 + (layer - 1) * NGH;
}

// ---------------- main kernel ----------------
__global__ void __launch_bounds__(NTH, 2)
spnn_mma_kernel(const float* __restrict__ nf,
                const float* __restrict__ geo,
                const int*   __restrict__ ei,
                const float* __restrict__ att,
                const float* __restrict__ b0,
                const float* __restrict__ bh,
                const float* __restrict__ gamma,
                const float* __restrict__ beta,
                const float* __restrict__ rmean,
                const float* __restrict__ rvar,
                float* __restrict__ out,
                int E)
{
    const int br  = blockIdx.y;
    const int cnt = g_cnt[br];
    const int m0  = blockIdx.x * TM;
    if (m0 >= cnt) return;

    extern __shared__ char sm[];
    const int tid = threadIdx.x;
    const int wid = tid >> 5, lid = tid & 31;
    const int wm = wid & 1, wn = wid >> 1;   // 2 m-warps x 4 n-warps

    int*   sI = (int*)(sm + OFF_SI);
    int*   sJ = (int*)(sm + OFF_SJ);
    int*   sK = (int*)(sm + OFF_SK);
    int*   sE = (int*)(sm + OFF_SE);
    float* sS = (float*)(sm + OFF_SS);
    float* sHt = (float*)(sm + OFF_SH);

    if (tid < TM) {
        int idx = m0 + tid;
        int e = (idx < cnt) ? g_list[br * E_CAP + idx] : g_list[br * E_CAP];
        sE[tid] = e;
        sI[tid] = ei[e];
        sJ[tid] = ei[E + e];
        sK[tid] = ei[2 * E + e];
    }

    prefetch_B(sm, 0, br, 0, tid);
    CP_COMMIT();

    const uint32_t smb = smem_u32(sm);

    float acc[2][8][4];
    #pragma unroll
    for (int mt = 0; mt < 2; mt++)
        #pragma unroll
        for (int nt = 0; nt < 8; nt++)
            #pragma unroll
            for (int q = 0; q < 4; q++) acc[mt][nt][q] = 0.f;

    int buf = 0;

    #pragma unroll 1
    for (int layer = 0; layer <= DEPTHL; layer++) {
        const int nch = (layer == 0) ? NG0 : NGH;

        #pragma unroll 1
        for (int kc = 0; kc < nch; kc++) {
            // prefetch next group (maybe next layer's group 0)
            int nlayer = layer, nkc = kc + 1;
            bool have_next = true;
            if (nkc == nch) {
                if (layer == DEPTHL) have_next = false;
                else { nlayer = layer + 1; nkc = 0; }
            }
            if (have_next) {
                prefetch_B(sm, buf ^ 1, br, layer_gbase(nlayer) + nkc, tid);
                CP_COMMIT();
                cp_wait<1>();
            } else {
                cp_wait<0>();
            }
            __syncthreads();

            // layer-0: gather + hi/lo split one k16 chunk into X (native layout)
            if (layer == 0) {
                int r = tid >> 2, q = tid & 3;
                float x0, x1, x2, x3;
                if (kc < 48) {
                    int seg = kc >> 4;
                    int idx = (seg == 0) ? sI[r] : (seg == 1) ? sJ[r] : sK[r];
                    const float* src = nf + (size_t)idx * HID + (kc & 15) * 16 + q * 4;
                    float4 v = *(const float4*)src;
                    x0 = v.x; x1 = v.y; x2 = v.z; x3 = v.w;
                } else {
                    int e = sE[r];
                    int c0 = q * 4;
                    x0 = (c0     < GEO) ? geo[(size_t)e * GEO + c0]     : 0.f;
                    x1 = (c0 + 1 < GEO) ? geo[(size_t)e * GEO + c0 + 1] : 0.f;
                    x2 = (c0 + 2 < GEO) ? geo[(size_t)e * GEO + c0 + 2] : 0.f;
                    x3 = (c0 + 3 < GEO) ? geo[(size_t)e * GEO + c0 + 3] : 0.f;
                }
                uint32_t h0, l0, h1, l1;
                cvt2(x0, x1, h0, l0);
                cvt2(x2, x3, h1, l1);
                int kh = q >> 1;
                int lrow = (r & 7) + ((r >> 3) & 1) * 8 + kh * 16;
                uint32_t off = (uint32_t)((r >> 4) * 512 + lrow * 16 + (q & 1) * 8);
                *(uint2*)(sm + OFF_X + off)        = make_uint2(h0, h1);
                *(uint2*)(sm + OFF_X + 2048 + off) = make_uint2(l0, l1);
                __syncthreads();
            }

            // A fragments for this k16 group
            uint32_t aH, aL;
            if (layer == 0) { aH = smb + OFF_X;             aL = aH + 2048;  }
            else            { aH = smb + OFF_H + kc * 2048; aL = aH + 32768; }
            uint32_t ahi[2][4], alo[2][4];
            #pragma unroll
            for (int mt = 0; mt < 2; mt++) {
                uint32_t off = (uint32_t)((wm * 2 + mt) * 512 + lid * 16);
                ldsm4(ahi[mt], aH + off);
                ldsm4(alo[mt], aL + off);
            }

            uint32_t bB = smb + OFF_B + buf * 16384;
            #pragma unroll
            for (int ntp = 0; ntp < 4; ntp++) {
                uint32_t off = (uint32_t)((wn * 4 + ntp) * 512 + lid * 16);
                uint32_t bh4[4], bl4[4];
                ldsm4(bh4, bB + off);
                ldsm4(bl4, bB + 8192 + off);
                #pragma unroll
                for (int mt = 0; mt < 2; mt++)
                    #pragma unroll
                    for (int s = 0; s < 2; s++) {
                        float* c = acc[mt][ntp * 2 + s];
                        mma16816(c, ahi[mt], bh4 + s * 2);
                        mma16816(c, alo[mt], bh4 + s * 2);
                        mma16816(c, ahi[mt], bl4 + s * 2);
                    }
            }
            __syncthreads();
            buf ^= 1;
        }

        // BN params for this layer
        {
            int c = tid;
            size_t o = ((size_t)br * (DEPTHL + 1) + layer) * HID + c;
            float sc = gamma[o] * rsqrtf(rvar[o] + EPSB);
            float bias = (layer == 0) ? b0[br * HID + c]
                                      : bh[(size_t)(br * DEPTHL + layer - 1) * HID + c];
            sS[c] = sc;
            sHt[c] = beta[o] - rmean[o] * sc + bias * sc;
        }
        __syncthreads();

        const bool fin = (layer == DEPTHL);
        float attb = fin ? att[br] : 0.f;
        #pragma unroll
        for (int mt = 0; mt < 2; mt++) {
            int r0 = wm * 32 + mt * 16 + (lid >> 2);
            int r1 = r0 + 8;
            #pragma unroll
            for (int nt = 0; nt < 8; nt++) {
                float* c = acc[mt][nt];
                int j0 = wn * 64 + nt * 8 + (lid & 3) * 2;
                float sc0 = sS[j0], sc1 = sS[j0 + 1];
                float h0 = sHt[j0], h1 = sHt[j0 + 1];
                float f00 = fmaxf(fmaf(c[0], sc0, h0), 0.f);
                float f01 = fmaxf(fmaf(c[1], sc1, h1), 0.f);
                float f10 = fmaxf(fmaf(c[2], sc0, h0), 0.f);
                float f11 = fmaxf(fmaf(c[3], sc1, h1), 0.f);
                c[0] = c[1] = c[2] = c[3] = 0.f;
                if (!fin) {
                    uint32_t hv0, lv0, hv1, lv1;
                    cvt2(f00, f01, hv0, lv0);
                    cvt2(f10, f11, hv1, lv1);
                    int kg = j0 >> 4, kh = (j0 >> 3) & 1;
                    int lr0 = (lid >> 2) + kh * 16;
                    uint32_t base = (uint32_t)(kg * 2048 + (wm * 2 + mt) * 512 + (j0 & 7) * 2);
                    uint32_t o0 = base + (uint32_t)(lr0 * 16);
                    uint32_t o1 = base + (uint32_t)((lr0 + 8) * 16);
                    *(uint32_t*)(sm + OFF_H + o0)         = hv0;
                    *(uint32_t*)(sm + OFF_H + 32768 + o0) = lv0;
                    *(uint32_t*)(sm + OFF_H + o1)         = hv1;
                    *(uint32_t*)(sm + OFF_H + 32768 + o1) = lv1;
                } else {
                    if (m0 + r0 < cnt) {
                        float* op = out + (size_t)sI[r0] * HID + j0;
                        atomicAdd(op,     f00 * attb);
                        atomicAdd(op + 1, f01 * attb);
                    }
                    if (m0 + r1 < cnt) {
                        float* op = out + (size_t)sI[r1] * HID + j0;
                        atomicAdd(op,     f10 * attb);
                        atomicAdd(op + 1, f11 * attb);
                    }
                }
            }
        }
        __syncthreads();
    }
}

extern "C" void kernel_launch(void* const* d_in, const int* in_sizes, int n_in,
                              void* d_out, int out_size) {
    const float* nf  = (const float*)d_in[0];
    const float* geo = (const float*)d_in[1];
    const int*   ei  = (const int*)d_in[2];
    const int*   eij = (const int*)d_in[3];
    const int*   ejk = (const int*)d_in[4];
    const float* att = (const float*)d_in[5];
    const float* W0  = (const float*)d_in[6];
    const float* b0  = (const float*)d_in[7];
    const float* Wh  = (const float*)d_in[8];
    const float* bh  = (const float*)d_in[9];
    const float* gam = (const float*)d_in[10];
    const float* bet = (const float*)d_in[11];
    const float* rme = (const float*)d_in[12];
    const float* rva = (const float*)d_in[13];
    const int*   nei = (const int*)d_in[14];

    int E = in_sizes[3];
    if (E > E_CAP) E = E_CAP;
    float* out = (float*)d_out;

    cudaMemsetAsync(out, 0, (size_t)out_size * sizeof(float));

    zero_cnt_kernel<<<1, 32>>>();
    bucket_kernel<<<(E + 255) / 256, 256>>>(eij, ejk, nei, E);

    int prep_total = NBR * KPB * HID;
    prep_w<<<(prep_total + 255) / 256, 256>>>(W0, Wh);

    cudaFuncSetAttribute(spnn_mma_kernel,
                         cudaFuncAttributeMaxDynamicSharedMemorySize, SMEM_BYTES);
    dim3 grid((E + TM - 1) / TM, NBR);
    spnn_mma_kernel<<<grid, NTH, SMEM_BYTES>>>(nf, geo, ei, att, b0, bh,
                                               gam, bet, rme, rva, out, E);
}

// round 11
// speedup vs baseline: 3.1515x; 1.0588x over previous
#include <cuda_runtime.h>
#include <cuda_bf16.h>
#include <stdint.h>

// ---------------- problem constants ----------------
#define HID    256
#define GEO    13
#define DIN    781
#define NBR    4
#define DEPTHL 3
#define EPSB   1e-5f
#define E_CAP  100000

// ---------------- tiling ----------------
#define TM    64
#define NTH   256
#define NG0   49                      // layer-0 k16 groups (49*16=784 >= 781)
#define KPAD0 (NG0*16)
#define NGH   16                      // k16 groups per hidden layer
#define NGT   (NG0 + DEPTHL*NGH)      // 97 groups per branch (linear)
#define KPB   (NGT*16)                // 1552
#define GRP_ELEMS 4096                // 16 ntiles x 32 rows x 8 bf16

// ---------------- smem offsets (bytes) ----------------
#define OFF_SI 0
#define OFF_SJ 256
#define OFF_SK 512
#define OFF_SE 768
#define OFF_H  1024                   // hi plane 32KB + lo plane 32KB
#define OFF_B  (OFF_H + 65536)       // 3 stages x 16KB
#define SMEM_BYTES (OFF_B + 49152)   // 115712  (<= 114KB for 2 CTA/SM)
// X ring aliases the start of H (dead during layer 0): 2 slots x 4KB

__device__ int g_cnt[NBR];
__device__ int g_list[NBR * E_CAP];
// packed ldmatrix-native weights: [br][group][ntile][32 rows][8 bf16]
__device__ __align__(16) __nv_bfloat16 g_Whi[NBR * NGT * GRP_ELEMS];
__device__ __align__(16) __nv_bfloat16 g_Wlo[NBR * NGT * GRP_ELEMS];
// pre-folded BN: scale & shift per [br][layer][col]
__device__ __align__(16) float g_bnS[NBR * (DEPTHL + 1) * HID];
__device__ __align__(16) float g_bnH[NBR * (DEPTHL + 1) * HID];

// ---------------- helpers ----------------
__device__ __forceinline__ uint32_t smem_u32(const void* p) {
    uint32_t a;
    asm("{ .reg .u64 t; cvta.to.shared.u64 t, %1; cvt.u32.u64 %0, t; }" : "=r"(a) : "l"(p));
    return a;
}
__device__ __forceinline__ void cp16(uint32_t dst, const void* src) {
    asm volatile("cp.async.cg.shared.global [%0], [%1], 16;" :: "r"(dst), "l"(src) : "memory");
}
#define CP_COMMIT() asm volatile("cp.async.commit_group;" ::: "memory")
template<int N> __device__ __forceinline__ void cp_wait() {
    asm volatile("cp.async.wait_group %0;" :: "n"(N) : "memory");
}
__device__ __forceinline__ void ldsm4(uint32_t* r, uint32_t a) {
    asm volatile("ldmatrix.sync.aligned.m8n8.x4.shared.b16 {%0,%1,%2,%3}, [%4];"
        : "=r"(r[0]), "=r"(r[1]), "=r"(r[2]), "=r"(r[3]) : "r"(a));
}
__device__ __forceinline__ void mma16816(float* c, const uint32_t* a, const uint32_t* b) {
    asm volatile("mma.sync.aligned.m16n8k16.row.col.f32.bf16.bf16.f32 "
        "{%0,%1,%2,%3}, {%4,%5,%6,%7}, {%8,%9}, {%0,%1,%2,%3};"
        : "+f"(c[0]), "+f"(c[1]), "+f"(c[2]), "+f"(c[3])
        : "r"(a[0]), "r"(a[1]), "r"(a[2]), "r"(a[3]), "r"(b[0]), "r"(b[1]));
}
__device__ __forceinline__ void cvt2(float a, float b, uint32_t& h, uint32_t& l) {
    __nv_bfloat16 ha = __float2bfloat16(a), hb = __float2bfloat16(b);
    __nv_bfloat16 la = __float2bfloat16(a - __bfloat162float(ha));
    __nv_bfloat16 lb = __float2bfloat16(b - __bfloat162float(hb));
    h = (uint32_t)__bfloat16_as_ushort(ha) | ((uint32_t)__bfloat16_as_ushort(hb) << 16);
    l = (uint32_t)__bfloat16_as_ushort(la) | ((uint32_t)__bfloat16_as_ushort(lb) << 16);
}

// ---------------- small kernels ----------------
__global__ void zero_cnt_kernel() {
    if (threadIdx.x < NBR) g_cnt[threadIdx.x] = 0;
}
__global__ void bucket_kernel(const int* __restrict__ edx_ij,
                              const int* __restrict__ edx_jk,
                              const int* __restrict__ nei, int E) {
    int e = blockIdx.x * blockDim.x + threadIdx.x;
    if (e >= E) return;
    int Ein = *nei;
    int br = ((edx_ij[e] < Ein) ? 0 : 2) + ((edx_jk[e] < Ein) ? 0 : 1);
    int pos = atomicAdd(&g_cnt[br], 1);
    g_list[br * E_CAP + pos] = e;
}

// Pack weights transposed + hi/lo split into ldmatrix-native layout.
__global__ void prep_w(const float* __restrict__ W0, const float* __restrict__ Wh) {
    int t = blockIdx.x * blockDim.x + threadIdx.x;
    if (t >= NBR * KPB * HID) return;
    int n = t & 255;
    int rem = t >> 8;
    int k = rem % KPB;
    int br = rem / KPB;
    float w;
    if (k < KPAD0) {
        w = (k < DIN) ? W0[((size_t)br * DIN + k) * HID + n] : 0.f;
    } else {
        int kk = k - KPAD0;
        int l = kk >> 8, k2 = kk & 255;
        w = Wh[(((size_t)(br * DEPTHL + l)) * HID + k2) * HID + n];
    }
    int g  = k >> 4;
    int kl = k & 15;
    int kh = kl >> 3, kb = kl & 7;
    int lrow = (n & 7) + ((n >> 3) & 1) * 16 + kh * 8;
    int ntile = n >> 4;
    size_t off = (((size_t)(br * NGT + g)) * 16 + ntile) * 256 + lrow * 8 + kb;
    __nv_bfloat16 h = __float2bfloat16(w);
    g_Whi[off] = h;
    g_Wlo[off] = __float2bfloat16(w - __bfloat162float(h));
}

// Pre-fold BN+bias into scale/shift tables.
__global__ void prep_bn(const float* __restrict__ b0, const float* __restrict__ bh,
                        const float* __restrict__ gamma, const float* __restrict__ beta,
                        const float* __restrict__ rmean, const float* __restrict__ rvar) {
    int t = blockIdx.x * blockDim.x + threadIdx.x;
    if (t >= NBR * (DEPTHL + 1) * HID) return;
    int c = t & 255;
    int rem = t >> 8;
    int layer = rem % (DEPTHL + 1);
    int br = rem / (DEPTHL + 1);
    float sc = gamma[t] * rsqrtf(rvar[t] + EPSB);
    float bias = (layer == 0) ? b0[br * HID + c]
                              : bh[(size_t)(br * DEPTHL + layer - 1) * HID + c];
    g_bnS[t] = sc;
    g_bnH[t] = beta[t] - rmean[t] * sc + bias * sc;
}

__device__ __forceinline__ void prefetch_B(uint32_t smb, int slot, int br, int g, int tid) {
    size_t base = (size_t)(br * NGT + g) * GRP_ELEMS;   // bf16 elems
    uint32_t d = smb + OFF_B + slot * 16384 + (uint32_t)tid * 16;
    const char* sh = (const char*)(g_Whi + base) + tid * 16;
    const char* sl = (const char*)(g_Wlo + base) + tid * 16;
    cp16(d,         sh);
    cp16(d + 4096,  sh + 4096);
    cp16(d + 8192,  sl);
    cp16(d + 12288, sl + 4096);
}

// Stage layer-0 A chunk kc into X slot (kc&1). tid -> row r=tid>>2, quad q=tid&3.
__device__ __forceinline__ void stage_X(char* sm, int kc,
                                        const float* __restrict__ nf,
                                        const float* __restrict__ geo,
                                        const int* sI, const int* sJ,
                                        const int* sK, const int* sE, int tid) {
    int r = tid >> 2, q = tid & 3;
    float x0, x1, x2, x3;
    if (kc < 48) {
        int seg = kc >> 4;
        int idx = (seg == 0) ? sI[r] : (seg == 1) ? sJ[r] : sK[r];
        const float* src = nf + (size_t)idx * HID + (kc & 15) * 16 + q * 4;
        float4 v = *(const float4*)src;
        x0 = v.x; x1 = v.y; x2 = v.z; x3 = v.w;
    } else {
        int e = sE[r];
        int c0 = q * 4;
        x0 = (c0     < GEO) ? geo[(size_t)e * GEO + c0]     : 0.f;
        x1 = (c0 + 1 < GEO) ? geo[(size_t)e * GEO + c0 + 1] : 0.f;
        x2 = (c0 + 2 < GEO) ? geo[(size_t)e * GEO + c0 + 2] : 0.f;
        x3 = (c0 + 3 < GEO) ? geo[(size_t)e * GEO + c0 + 3] : 0.f;
    }
    uint32_t h0, l0, h1, l1;
    cvt2(x0, x1, h0, l0);
    cvt2(x2, x3, h1, l1);
    int kh = q >> 1;
    int lrow = (r & 7) + ((r >> 3) & 1) * 8 + kh * 16;
    uint32_t off = (uint32_t)((r >> 4) * 512 + lrow * 16 + (q & 1) * 8);
    char* slot = sm + OFF_H + (kc & 1) * 4096;
    *(uint2*)(slot + off)        = make_uint2(h0, h1);
    *(uint2*)(slot + 2048 + off) = make_uint2(l0, l1);
}

// ---------------- main kernel ----------------
__global__ void __launch_bounds__(NTH, 2)
spnn_mma_kernel(const float* __restrict__ nf,
                const float* __restrict__ geo,
                const int*   __restrict__ ei,
                const float* __restrict__ att,
                float* __restrict__ out,
                int E)
{
    const int br  = blockIdx.y;
    const int cnt = g_cnt[br];
    const int m0  = blockIdx.x * TM;
    if (m0 >= cnt) return;

    extern __shared__ char sm[];
    const int tid = threadIdx.x;
    const int wid = tid >> 5, lid = tid & 31;
    const int wm = wid & 1, wn = wid >> 1;   // 2 m-warps x 4 n-warps

    int* sI = (int*)(sm + OFF_SI);
    int* sJ = (int*)(sm + OFF_SJ);
    int* sK = (int*)(sm + OFF_SK);
    int* sE = (int*)(sm + OFF_SE);

    const uint32_t smb = smem_u32(sm);

    if (tid < TM) {
        int idx = m0 + tid;
        int e = (idx < cnt) ? g_list[br * E_CAP + idx] : g_list[br * E_CAP];
        sE[tid] = e;
        sI[tid] = ei[e];
        sJ[tid] = ei[E + e];
        sK[tid] = ei[2 * E + e];
    }

    // prologue: B groups 0 and 1 in flight (slots 0, 1)
    prefetch_B(smb, 0, br, 0, tid);
    CP_COMMIT();
    prefetch_B(smb, 1, br, 1, tid);
    CP_COMMIT();

    __syncthreads();                 // idx visible
    stage_X(sm, 0, nf, geo, sI, sJ, sK, sE, tid);   // X_0 into slot 0

    float acc[2][8][4];
    #pragma unroll
    for (int mt = 0; mt < 2; mt++)
        #pragma unroll
        for (int nt = 0; nt < 8; nt++)
            #pragma unroll
            for (int q = 0; q < 4; q++) acc[mt][nt][q] = 0.f;

    int gidx = 0;

    #pragma unroll 1
    for (int layer = 0; layer <= DEPTHL; layer++) {
        const int nch = (layer == 0) ? NG0 : NGH;

        #pragma unroll 1
        for (int kc = 0; kc < nch; kc++) {
            if (gidx == NGT - 1) cp_wait<0>(); else cp_wait<1>();
            __syncthreads();

            // stage next layer-0 A chunk into the other X slot (no barrier needed)
            if (layer == 0 && kc < NG0 - 1)
                stage_X(sm, kc + 1, nf, geo, sI, sJ, sK, sE, tid);

            // prefetch B group gidx+2 into slot (gidx+2)%3
            if (gidx + 2 < NGT) {
                prefetch_B(smb, (gidx + 2) % 3, br, gidx + 2, tid);
                CP_COMMIT();
            }

            // A fragments
            uint32_t aH, aL;
            if (layer == 0) {
                aH = smb + OFF_H + (uint32_t)((kc & 1) * 4096);
                aL = aH + 2048;
            } else {
                aH = smb + OFF_H + (uint32_t)(kc * 2048);
                aL = aH + 32768;
            }
            uint32_t ahi[2][4], alo[2][4];
            #pragma unroll
            for (int mt = 0; mt < 2; mt++) {
                uint32_t off = (uint32_t)((wm * 2 + mt) * 512 + lid * 16);
                ldsm4(ahi[mt], aH + off);
                ldsm4(alo[mt], aL + off);
            }

            uint32_t bB = smb + OFF_B + (uint32_t)((gidx % 3) * 16384);
            #pragma unroll
            for (int ntp = 0; ntp < 4; ntp++) {
                uint32_t off = (uint32_t)((wn * 4 + ntp) * 512 + lid * 16);
                uint32_t bh4[4], bl4[4];
                ldsm4(bh4, bB + off);
                ldsm4(bl4, bB + 8192 + off);
                #pragma unroll
                for (int mt = 0; mt < 2; mt++)
                    #pragma unroll
                    for (int s = 0; s < 2; s++) {
                        float* c = acc[mt][ntp * 2 + s];
                        mma16816(c, ahi[mt], bh4 + s * 2);
                        mma16816(c, alo[mt], bh4 + s * 2);
                        mma16816(c, ahi[mt], bl4 + s * 2);
                    }
            }
            gidx++;
        }

        __syncthreads();   // all reads of H/X done before epilogue writes H

        const bool fin = (layer == DEPTHL);
        const float* bnS = g_bnS + (size_t)(br * (DEPTHL + 1) + layer) * HID;
        const float* bnH = g_bnH + (size_t)(br * (DEPTHL + 1) + layer) * HID;
        float attb = fin ? att[br] : 0.f;

        #pragma unroll
        for (int mt = 0; mt < 2; mt++) {
            int r0 = wm * 32 + mt * 16 + (lid >> 2);
            int r1 = r0 + 8;
            #pragma unroll
            for (int nt = 0; nt < 8; nt++) {
                float* c = acc[mt][nt];
                int j0 = wn * 64 + nt * 8 + (lid & 3) * 2;
                float2 scv = *(const float2*)(bnS + j0);
                float2 shv = *(const float2*)(bnH + j0);
                float f00 = fmaxf(fmaf(c[0], scv.x, shv.x), 0.f);
                float f01 = fmaxf(fmaf(c[1], scv.y, shv.y), 0.f);
                float f10 = fmaxf(fmaf(c[2], scv.x, shv.x), 0.f);
                float f11 = fmaxf(fmaf(c[3], scv.y, shv.y), 0.f);
                c[0] = c[1] = c[2] = c[3] = 0.f;
                if (!fin) {
                    uint32_t hv0, lv0, hv1, lv1;
                    cvt2(f00, f01, hv0, lv0);
                    cvt2(f10, f11, hv1, lv1);
                    int kg = j0 >> 4, kh = (j0 >> 3) & 1;
                    int lr0 = (lid >> 2) + kh * 16;
                    uint32_t base = (uint32_t)(kg * 2048 + (wm * 2 + mt) * 512 + (j0 & 7) * 2);
                    uint32_t o0 = base + (uint32_t)(lr0 * 16);
                    uint32_t o1 = base + (uint32_t)((lr0 + 8) * 16);
                    *(uint32_t*)(sm + OFF_H + o0)         = hv0;
                    *(uint32_t*)(sm + OFF_H + 32768 + o0) = lv0;
                    *(uint32_t*)(sm + OFF_H + o1)         = hv1;
                    *(uint32_t*)(sm + OFF_H + 32768 + o1) = lv1;
                } else {
                    if (m0 + r0 < cnt) {
                        float* op = out + (size_t)sI[r0] * HID + j0;
                        atomicAdd(op,     f00 * attb);
                        atomicAdd(op + 1, f01 * attb);
                    }
                    if (m0 + r1 < cnt) {
                        float* op = out + (size_t)sI[r1] * HID + j0;
                        atomicAdd(op,     f10 * attb);
                        atomicAdd(op + 1, f11 * attb);
                    }
                }
            }
        }
        // next layer's first group sync orders these writes vs. reads
    }
}

extern "C" void kernel_launch(void* const* d_in, const int* in_sizes, int n_in,
                              void* d_out, int out_size) {
    const float* nf  = (const float*)d_in[0];
    const float* geo = (const float*)d_in[1];
    const int*   ei  = (const int*)d_in[2];
    const int*   eij = (const int*)d_in[3];
    const int*   ejk = (const int*)d_in[4];
    const float* att = (const float*)d_in[5];
    const float* W0  = (const float*)d_in[6];
    const float* b0  = (const float*)d_in[7];
    const float* Wh  = (const float*)d_in[8];
    const float* bh  = (const float*)d_in[9];
    const float* gam = (const float*)d_in[10];
    const float* bet = (const float*)d_in[11];
    const float* rme = (const float*)d_in[12];
    const float* rva = (const float*)d_in[13];
    const int*   nei = (const int*)d_in[14];

    int E = in_sizes[3];
    if (E > E_CAP) E = E_CAP;
    float* out = (float*)d_out;

    cudaMemsetAsync(out, 0, (size_t)out_size * sizeof(float));

    zero_cnt_kernel<<<1, 32>>>();
    bucket_kernel<<<(E + 255) / 256, 256>>>(eij, ejk, nei, E);

    int prep_total = NBR * KPB * HID;
    prep_w<<<(prep_total + 255) / 256, 256>>>(W0, Wh);
    int bn_total = NBR * (DEPTHL + 1) * HID;
    prep_bn<<<(bn_total + 255) / 256, 256>>>(b0, bh, gam, bet, rme, rva);

    cudaFuncSetAttribute(spnn_mma_kernel,
                         cudaFuncAttributeMaxDynamicSharedMemorySize, SMEM_BYTES);
    dim3 grid((E + TM - 1) / TM, NBR);
    spnn_mma_kernel<<<grid, NTH, SMEM_BYTES>>>(nf, geo, ei, att, out, E);
}